// round 2
// baseline (speedup 1.0000x reference)
#include <cuda_runtime.h>

// Resample2d (FlowNet2 bilinear warp), fixed shape B=4, C=64, H=384, W=512.
// input1: [B, C, H, W] float32
// flow  : [B, 2, H, W] float32 (dx, dy)
// out   : [B, C, H, W] float32
//
// One thread per output pixel (b, y, x). Flow, bilinear weights and the 4
// clamped tap indices are computed once, then reused across all 64 channels.
// Writes are fully coalesced; gather reads are near-coalesced since flow is
// small (~N(0,1) px), so L2 absorbs the overlap.

static constexpr int B = 4;
static constexpr int C = 64;
static constexpr int H = 384;
static constexpr int W = 512;
static constexpr int HW = H * W;
static constexpr int NPIX = B * H * W;

__global__ __launch_bounds__(256) void resample2d_kernel(
    const float* __restrict__ in1,
    const float* __restrict__ flow,
    float* __restrict__ out)
{
    int idx = blockIdx.x * blockDim.x + threadIdx.x;
    if (idx >= NPIX) return;

    int x = idx & (W - 1);          // W = 512 = 2^9
    int t = idx >> 9;               // b*H + y
    int y = t % H;
    int b = t / H;

    const float* fb = flow + (size_t)b * 2 * HW;
    int pix = y * W + x;
    float dx = fb[pix];
    float dy = fb[HW + pix];

    float xf = (float)x + dx;
    float yf = (float)y + dy;
    float x0f = floorf(xf);
    float y0f = floorf(yf);
    float a  = xf - x0f;            // frac x
    float bw = yf - y0f;            // frac y

    int x0i = (int)x0f;
    int y0i = (int)y0f;
    int x0 = min(max(x0i,     0), W - 1);
    int x1 = min(max(x0i + 1, 0), W - 1);
    int y0 = min(max(y0i,     0), H - 1);
    int y1 = min(max(y0i + 1, 0), H - 1);

    float w00 = (1.0f - a) * (1.0f - bw);
    float w10 = a * (1.0f - bw);
    float w01 = (1.0f - a) * bw;
    float w11 = a * bw;

    int i00 = y0 * W + x0;
    int i10 = y0 * W + x1;
    int i01 = y1 * W + x0;
    int i11 = y1 * W + x1;

    const float* p = in1 + (size_t)b * C * HW;
    float*       o = out + (size_t)b * C * HW + pix;

    #pragma unroll 4
    for (int c = 0; c < C; ++c) {
        size_t off = (size_t)c * HW;
        float v00 = __ldg(p + off + i00);
        float v10 = __ldg(p + off + i10);
        float v01 = __ldg(p + off + i01);
        float v11 = __ldg(p + off + i11);
        o[off] = w00 * v00 + w10 * v10 + w01 * v01 + w11 * v11;
    }
}

extern "C" void kernel_launch(void* const* d_in, const int* in_sizes, int n_in,
                              void* d_out, int out_size)
{
    const float* in1  = (const float*)d_in[0];
    const float* flow = (const float*)d_in[1];
    float*       out  = (float*)d_out;

    int threads = 256;
    int blocks = (NPIX + threads - 1) / threads;
    resample2d_kernel<<<blocks, threads>>>(in1, flow, out);
}